// round 5
// baseline (speedup 1.0000x reference)
#include <cuda_runtime.h>
#include <cuda_bf16.h>

// RippleNet: H=2, B=2048, M=64, D=16, N_ENT=500000, N_REL=32
// inputs: items[B] i32, heads[H,B,M] i32, relations[H,B,M] i32,
//         tails[H,B,M] i32, ent_emb[N_ENT,16] f32, rel_emb[32,16,16] f32
// output: predicts[B] f32

#define H_ 2
#define B_ 2048
#define M_ 64
#define D_ 16
#define NREL_ 32
#define QS 20   // q row stride in floats (float4-aligned, low-conflict)

// One block per b, 512 threads. Quad (4 lanes) = one row (128 rows total).
// Each thread: ONE head-chunk + ONE tail-chunk -> small front-batch (low
// MLP_p1 per thread), low regs, 3 CTAs/SM, 48 warps resident.
__global__ __launch_bounds__(512, 3) void ripple_kernel(
    const int* __restrict__ items,
    const int* __restrict__ heads,
    const int* __restrict__ rels,
    const int* __restrict__ tails,
    const float* __restrict__ ent,
    const float* __restrict__ rel,
    float* __restrict__ out)
{
    const int b   = blockIdx.x;
    const int tid = threadIdx.x;     // 0..511
    const int row = tid >> 2;        // 0..127 ; rows 0..63 hop0, 64..127 hop1
    const int ch  = tid & 3;
    const int j0  = ch * 4;

    __shared__ float  item_s[D_];
    __shared__ float  q[NREL_ * QS];
    __shared__ float2 wsum[16];      // per-warp {se, ses}; warps 0..7 hop0, 8..15 hop1

    const int it = items[b];
    if (tid < D_) item_s[tid] = ent[(size_t)it * D_ + tid];

    // ---- indices (quad-broadcast, coalesced within warp) ----
    const int base = (row >> 6) * (B_ * M_) + b * M_ + (row & 63);
    const int hidx = heads[base];
    const int ridx = rels[base];
    const int tidx = tails[base];

    // ---- gathers: one head chunk + one tail chunk + item chunk ----
    const float4 vi = *(const float4*)(ent + (size_t)it   * D_ + j0);
    const float4 hv = *(const float4*)(ent + (size_t)hidx * D_ + j0);
    const float4 tv = *(const float4*)(ent + (size_t)tidx * D_ + j0);

    __syncthreads();   // item_s ready; gathers still in flight

    // ---- q[r][j0..j0+3] on warps 0..3 (overlaps gather latency) ----
    if (tid < 128) {
        const int r  = tid >> 2;
        const float4* Rp = (const float4*)(rel + r * (D_ * D_)) + (tid & 3);
        float4 acc = make_float4(0.f, 0.f, 0.f, 0.f);
        #pragma unroll
        for (int i = 0; i < D_; i++) {
            const float4 rv = Rp[i * 4];
            const float  wi = item_s[i];
            acc.x = fmaf(wi, rv.x, acc.x);
            acc.y = fmaf(wi, rv.y, acc.y);
            acc.z = fmaf(wi, rv.z, acc.z);
            acc.w = fmaf(wi, rv.w, acc.w);
        }
        *(float4*)&q[r * QS + (tid & 3) * 4] = acc;
    }

    // ---- tail dot (independent of q) ----
    float s = fmaf(vi.x, tv.x, fmaf(vi.y, tv.y, fmaf(vi.z, tv.z, vi.w * tv.w)));
    s += __shfl_xor_sync(0xffffffffu, s, 1);
    s += __shfl_xor_sync(0xffffffffu, s, 2);

    __syncthreads();   // q ready

    // ---- head dot -> logit ----
    const float4 w4 = *(const float4*)&q[ridx * QS + j0];
    float l = fmaf(w4.x, hv.x, fmaf(w4.y, hv.y, fmaf(w4.z, hv.z, w4.w * hv.w)));
    l += __shfl_xor_sync(0xffffffffu, l, 1);
    l += __shfl_xor_sync(0xffffffffu, l, 2);

    // ---- softmax w/o max subtraction (|l| ~ 0.1; exp safe, same math) ----
    const float e = __expf(l);
    float se  = e;
    float ses = e * s;
    // lanes within a quad identical -> reduce offsets 16,8,4 only
    #pragma unroll
    for (int off = 16; off >= 4; off >>= 1) {
        se  += __shfl_xor_sync(0xffffffffu, se,  off);
        ses += __shfl_xor_sync(0xffffffffu, ses, off);
    }
    if ((tid & 31) == 0)
        wsum[tid >> 5] = make_float2(se, ses);
    __syncthreads();

    if (tid == 0) {
        float SE0 = 0.f, SES0 = 0.f, SE1 = 0.f, SES1 = 0.f;
        #pragma unroll
        for (int i = 0; i < 8; i++) {
            const float2 a = wsum[i];      SE0 += a.x; SES0 += a.y;
            const float2 c = wsum[8 + i];  SE1 += c.x; SES1 += c.y;
        }
        // 4x quad-lane replication cancels in each ratio
        const float x = SES0 / SE0 + SES1 / SE1;
        out[b] = 1.f / (1.f + __expf(-x));
    }
}

extern "C" void kernel_launch(void* const* d_in, const int* in_sizes, int n_in,
                              void* d_out, int out_size) {
    const int*   items = (const int*)  d_in[0];
    const int*   heads = (const int*)  d_in[1];
    const int*   rels  = (const int*)  d_in[2];
    const int*   tails = (const int*)  d_in[3];
    const float* ent   = (const float*)d_in[4];
    const float* rel   = (const float*)d_in[5];
    float* out = (float*)d_out;

    ripple_kernel<<<B_, 512>>>(items, heads, rels, tails, ent, rel, out);
}

// round 7
// speedup vs baseline: 1.1401x; 1.1401x over previous
#include <cuda_runtime.h>
#include <cuda_bf16.h>
#include <cstdint>

// RippleNet: H=2, B=2048, M=64, D=16, N_ENT=500000, N_REL=32
// inputs: items[B] i32, heads[H,B,M] i32, relations[H,B,M] i32,
//         tails[H,B,M] i32, ent_emb[N_ENT,16] f32, rel_emb[32,16,16] f32
// output: predicts[B] f32

#define H_ 2
#define B_ 2048
#define M_ 64
#define D_ 16
#define NREL_ 32
#define QS 20   // q row stride in floats: float4-aligned, low bank conflict

// ld.global.nc.v4 with L2 cache-hint policy (evict_last for the ent table)
__device__ __forceinline__ float4 ldg_policy_f4(const float* p, unsigned long long pol) {
    float4 v;
    asm volatile("ld.global.nc.L2::cache_hint.v4.f32 {%0,%1,%2,%3}, [%4], %5;"
                 : "=f"(v.x), "=f"(v.y), "=f"(v.z), "=f"(v.w)
                 : "l"(p), "l"(pol));
    return v;
}
__device__ __forceinline__ int ldg_policy_s32(const int* p, unsigned long long pol) {
    int v;
    asm volatile("ld.global.nc.L2::cache_hint.s32 %0, [%1], %2;"
                 : "=r"(v) : "l"(p), "l"(pol));
    return v;
}

// One block per b, 128 threads. Quad (4 lanes) cooperates on one 64B entity
// row. Thread (quad,ch) owns rows {quad, quad+32, quad+64, quad+96}, chunk ch.
__global__ __launch_bounds__(128, 8) void ripple_kernel(
    const int* __restrict__ items,
    const int* __restrict__ heads,
    const int* __restrict__ rels,
    const int* __restrict__ tails,
    const float* __restrict__ ent,
    const float* __restrict__ rel,
    float* __restrict__ out)
{
    const int b    = blockIdx.x;
    const int tid  = threadIdx.x;
    const int quad = tid >> 2;
    const int ch   = tid & 3;
    const int j0   = ch * 4;

    __shared__ float  item_s[D_];
    __shared__ float  q[NREL_ * QS];
    __shared__ float4 wsum[4];        // per-warp {se0, ses0, se1, ses1}

    // L2 policies: keep the 32MB ent table resident; index streams evict first.
    unsigned long long pol_keep, pol_stream;
    asm volatile("createpolicy.fractional.L2::evict_last.b64 %0, 1.0;"  : "=l"(pol_keep));
    asm volatile("createpolicy.fractional.L2::evict_first.b64 %0, 1.0;" : "=l"(pol_stream));

    const int it = items[b];
    if (tid < D_) item_s[tid] = __ldg(ent + (size_t)it * D_ + tid);

    // ---- index loads (quad-broadcast, coalesced) ----
    int hidx[4], ridx[4], tidx[4];
    #pragma unroll
    for (int k = 0; k < 4; k++) {
        const int row  = quad + 32 * k;
        const int base = (row >> 6) * (B_ * M_) + b * M_ + (row & 63);
        hidx[k] = ldg_policy_s32(heads + base, pol_stream);
        ridx[k] = ldg_policy_s32(rels  + base, pol_stream);
        tidx[k] = ldg_policy_s32(tails + base, pol_stream);
    }

    // ---- front-batch all embedding gathers (quad-coalesced, high MLP) ----
    const float4 vi = ldg_policy_f4(ent + (size_t)it * D_ + j0, pol_keep);
    float4 hv[4], tv[4];
    #pragma unroll
    for (int k = 0; k < 4; k++)
        hv[k] = ldg_policy_f4(ent + (size_t)hidx[k] * D_ + j0, pol_keep);
    #pragma unroll
    for (int k = 0; k < 4; k++)
        tv[k] = ldg_policy_f4(ent + (size_t)tidx[k] * D_ + j0, pol_keep);

    __syncthreads();   // item_s ready; in-flight gathers keep flying

    // ---- q[r][j0..j0+3] = sum_i item[i] * R_r[i][j0..j0+3]  (r = quad) ----
    {
        const float4* Rp = (const float4*)(rel + quad * (D_ * D_)) + ch;
        float4 acc = make_float4(0.f, 0.f, 0.f, 0.f);
        #pragma unroll
        for (int i = 0; i < D_; i++) {
            const float4 rv = Rp[i * 4];
            const float  wi = item_s[i];
            acc.x = fmaf(wi, rv.x, acc.x);
            acc.y = fmaf(wi, rv.y, acc.y);
            acc.z = fmaf(wi, rv.z, acc.z);
            acc.w = fmaf(wi, rv.w, acc.w);
        }
        *(float4*)&q[quad * QS + j0] = acc;
    }

    // ---- tail dots first (tv dies early -> lower register peak) ----
    float s[4];
    #pragma unroll
    for (int k = 0; k < 4; k++) {
        float ps = fmaf(vi.x, tv[k].x, fmaf(vi.y, tv[k].y,
                   fmaf(vi.z, tv[k].z, vi.w * tv[k].w)));
        ps += __shfl_xor_sync(0xffffffffu, ps, 1);
        ps += __shfl_xor_sync(0xffffffffu, ps, 2);
        s[k] = ps;
    }

    __syncthreads();   // q ready

    // ---- head dots: logit via q[ridx] (LDS.128) ----
    float l[4];
    #pragma unroll
    for (int k = 0; k < 4; k++) {
        const float4 w = *(const float4*)&q[ridx[k] * QS + j0];
        float p = fmaf(w.x, hv[k].x, fmaf(w.y, hv[k].y,
                  fmaf(w.z, hv[k].z, w.w * hv[k].w)));
        p += __shfl_xor_sync(0xffffffffu, p, 1);
        p += __shfl_xor_sync(0xffffffffu, p, 2);
        l[k] = p;
    }

    // ---- softmax w/o max subtraction (|l| ~ 0.1; exp safe, identical math) ----
    const float e0 = __expf(l[0]), e1 = __expf(l[1]);
    const float e2 = __expf(l[2]), e3 = __expf(l[3]);
    float se0  = e0 + e1;
    float ses0 = fmaf(e0, s[0], e1 * s[1]);
    float se1  = e2 + e3;
    float ses1 = fmaf(e2, s[2], e3 * s[3]);

    // lanes within a quad hold identical values -> reduce offsets 16,8,4 only
    #pragma unroll
    for (int off = 16; off >= 4; off >>= 1) {
        se0  += __shfl_xor_sync(0xffffffffu, se0,  off);
        ses0 += __shfl_xor_sync(0xffffffffu, ses0, off);
        se1  += __shfl_xor_sync(0xffffffffu, se1,  off);
        ses1 += __shfl_xor_sync(0xffffffffu, ses1, off);
    }
    if ((tid & 31) == 0)
        wsum[tid >> 5] = make_float4(se0, ses0, se1, ses1);
    __syncthreads();

    if (tid == 0) {
        float SE0 = 0.f, SES0 = 0.f, SE1 = 0.f, SES1 = 0.f;
        #pragma unroll
        for (int i = 0; i < 4; i++) {
            const float4 v = wsum[i];
            SE0 += v.x; SES0 += v.y; SE1 += v.z; SES1 += v.w;
        }
        // 4x quad-lane replication cancels in each ratio
        const float x = SES0 / SE0 + SES1 / SE1;
        out[b] = 1.f / (1.f + __expf(-x));
    }
}

extern "C" void kernel_launch(void* const* d_in, const int* in_sizes, int n_in,
                              void* d_out, int out_size) {
    const int*   items = (const int*)  d_in[0];
    const int*   heads = (const int*)  d_in[1];
    const int*   rels  = (const int*)  d_in[2];
    const int*   tails = (const int*)  d_in[3];
    const float* ent   = (const float*)d_in[4];
    const float* rel   = (const float*)d_in[5];
    float* out = (float*)d_out;

    ripple_kernel<<<B_, 128>>>(items, heads, rels, tails, ent, rel, out);
}